// round 9
// baseline (speedup 1.0000x reference)
#include <cuda_runtime.h>
#include <cstdint>

#define BATCH 8
#define NPIX  4096
#define CQK   128
#define CV    256

// ---- scratch (device globals: no runtime allocation allowed) ----
__device__ float g_Q[BATCH * NPIX * CQK];   // [b][i][c], pre-scaled by log2(e)
__device__ float g_K[BATCH * NPIX * CQK];   // [b][j][c]
__device__ float g_V[BATCH * NPIX * CV];    // [b][j][c]

// ============================================================================
// packed f32x2 FMA/MUL (sm_103a): 2 fp32 MACs per issue slot.
// ============================================================================
__device__ __forceinline__ void ffma2(float2& d, const float2 a, const float2 b) {
    asm("fma.rn.f32x2 %0, %1, %2, %0;"
        : "+l"(reinterpret_cast<unsigned long long&>(d))
        : "l"(reinterpret_cast<const unsigned long long&>(a)),
          "l"(reinterpret_cast<const unsigned long long&>(b)));
}
__device__ __forceinline__ void fmul2(float2& d, const float2 a) {
    asm("mul.rn.f32x2 %0, %0, %1;"
        : "+l"(reinterpret_cast<unsigned long long&>(d))
        : "l"(reinterpret_cast<const unsigned long long&>(a)));
}

// ============================================================================
// fast exp2 on the FMA pipe
// ============================================================================
__device__ __forceinline__ float exp2_fast(float x) {
    x = fmaxf(x, -126.0f);
    float fl = floorf(x);
    float f  = x - fl;
    float p  = 1.87757667e-3f;
    p = fmaf(p, f, 8.98934058e-3f);
    p = fmaf(p, f, 5.58263180e-2f);
    p = fmaf(p, f, 2.40153617e-1f);
    p = fmaf(p, f, 6.93153073e-1f);
    p = fmaf(p, f, 9.99999994e-1f);
    int e = (int)fl;
    float sc = __int_as_float((e + 127) << 23);
    return p * sc;
}

// ============================================================================
// Projection GEMM: out[b][i][o] = sum_k W[o][k] * in[b][k][i] + bias[o], *scale
// ============================================================================
template<int CIN, int COUT>
__global__ __launch_bounds__(256) void proj_kernel(
    const float* __restrict__ in, const float* __restrict__ W,
    const float* __restrict__ bias, float* __restrict__ out, float scale)
{
    __shared__ float sIn[32][64];   // [k][i]
    __shared__ float sWT[32][64];   // [k][o]
    __shared__ float sOut[64][64];  // [i][o]

    const int b  = blockIdx.z;
    const int i0 = blockIdx.x * 64;
    const int o0 = blockIdx.y * 64;
    const int tx = threadIdx.x;
    const int ti = tx & 15;
    const int to = tx >> 4;

    const float* inb = in + (size_t)b * CIN * NPIX + i0;

    float acc[4][4];
#pragma unroll
    for (int a = 0; a < 4; a++)
#pragma unroll
        for (int c = 0; c < 4; c++) acc[a][c] = 0.0f;

    for (int k0 = 0; k0 < CIN; k0 += 32) {
        for (int t = tx; t < 32 * 64 / 4; t += 256) {
            int k  = t >> 4;
            int i4 = (t & 15) << 2;
            *(float4*)&sIn[k][i4] = *(const float4*)&inb[(size_t)(k0 + k) * NPIX + i4];
        }
        for (int t = tx; t < 64 * 32 / 4; t += 256) {
            int o  = t >> 3;
            int k4 = (t & 7) << 2;
            float4 w = *(const float4*)&W[(size_t)(o0 + o) * CIN + k0 + k4];
            sWT[k4 + 0][o] = w.x; sWT[k4 + 1][o] = w.y;
            sWT[k4 + 2][o] = w.z; sWT[k4 + 3][o] = w.w;
        }
        __syncthreads();
#pragma unroll
        for (int k = 0; k < 32; k++) {
            float4 a = *(float4*)&sIn[k][ti * 4];
            float4 w = *(float4*)&sWT[k][to * 4];
            float av[4] = {a.x, a.y, a.z, a.w};
            float wv[4] = {w.x, w.y, w.z, w.w};
#pragma unroll
            for (int ii = 0; ii < 4; ii++)
#pragma unroll
                for (int oo = 0; oo < 4; oo++)
                    acc[ii][oo] = fmaf(av[ii], wv[oo], acc[ii][oo]);
        }
        __syncthreads();
    }

#pragma unroll
    for (int ii = 0; ii < 4; ii++)
#pragma unroll
        for (int oo = 0; oo < 4; oo++)
            sOut[ti * 4 + ii][to * 4 + oo] = acc[ii][oo];
    __syncthreads();

    for (int t = tx; t < 64 * 64 / 4; t += 256) {
        int i  = t >> 4;
        int o4 = (t & 15) << 2;
        float4 v = *(float4*)&sOut[i][o4];
        float4 bb = *(const float4*)&bias[o0 + o4];
        v.x = (v.x + bb.x) * scale;
        v.y = (v.y + bb.y) * scale;
        v.z = (v.z + bb.z) * scale;
        v.w = (v.w + bb.w) * scale;
        *(float4*)&out[((size_t)b * NPIX + i0 + i) * COUT + o0 + o4] = v;
    }
}

// ============================================================================
// Flash attention + fuse — 512 threads (16 warps) for latency hiding.
//   QK micro-tile 2x4 per thread (i = ti + 32*ii, j = tj + 16*jj).
//   PV channel map: c = 64*chunk + tj*4 + e (conflict-free 16B lane stride).
// ============================================================================
#define BI 64
#define BJ 64
#define NT 512
#define SQ_STR 132   // 128 + 4 pad
#define SV_STR 256
#define SS_STR 68    // 64 + 4 pad

#define SMEM_FLOATS (BI*SQ_STR + BJ*SQ_STR + BJ*SV_STR + BI*SS_STR + 3*BI)
#define SMEM_BYTES  (SMEM_FLOATS * 4)

__global__ __launch_bounds__(NT, 1) void flash_kernel(
    const float* __restrict__ Q, const float* __restrict__ K,
    const float* __restrict__ V, const float* __restrict__ motion,
    float* __restrict__ out)
{
    extern __shared__ float smem[];
    float* sQ = smem;                      // [BI][SQ_STR]
    float* sK = sQ + BI * SQ_STR;          // [BJ][SQ_STR]
    float* sV = sK + BJ * SQ_STR;          // [BJ][SV_STR]
    float* sS = sV + BJ * SV_STR;          // [BI][SS_STR]
    float* sM = sS + BI * SS_STR;
    float* sL = sM + BI;
    float* sScale = sL + BI;

    const int b  = blockIdx.y;
    const int i0 = blockIdx.x * BI;
    const int tx = threadIdx.x;
    const int ti = tx >> 4;    // 0..31
    const int tj = tx & 15;    // 0..15

    const float* Qb = Q + ((size_t)b * NPIX + i0) * CQK;
    const float* Kb = K + (size_t)b * NPIX * CQK;
    const float* Vb = V + (size_t)b * NPIX * CV;

    // load Q tile once
    for (int t = tx; t < BI * CQK / 4; t += NT) {
        int i  = t >> 5;
        int k4 = (t & 31) << 2;
        *(float4*)&sQ[i * SQ_STR + k4] = *(const float4*)&Qb[(size_t)i * CQK + k4];
    }
    if (tx < BI) { sM[tx] = -1e30f; sL[tx] = 0.0f; }

    // accumulators: i = ti + 32*ii ; c = 64*(cc>>1) + tj*4 + 2*(cc&1) + {0,1}
    float2 acc[2][8];
#pragma unroll
    for (int ii = 0; ii < 2; ii++)
#pragma unroll
        for (int cc = 0; cc < 8; cc++) acc[ii][cc] = make_float2(0.0f, 0.0f);

    for (int j0 = 0; j0 < NPIX; j0 += BJ) {
        // ---- load K, V tiles ----
        for (int t = tx; t < BJ * CQK / 4; t += NT) {
            int j  = t >> 5;
            int k4 = (t & 31) << 2;
            *(float4*)&sK[j * SQ_STR + k4] = *(const float4*)&Kb[(size_t)(j0 + j) * CQK + k4];
        }
        for (int t = tx; t < BJ * CV / 4; t += NT) {
            int j  = t >> 6;
            int c4 = (t & 63) << 2;
            *(float4*)&sV[j * SV_STR + c4] = *(const float4*)&Vb[(size_t)(j0 + j) * CV + c4];
        }
        __syncthreads();

        // ---- S = Q Kt : 2x4 micro-tile, float2 accumulators along k ----
        {
            float2 sacc[2][4];
#pragma unroll
            for (int a = 0; a < 2; a++)
#pragma unroll
                for (int c = 0; c < 4; c++) sacc[a][c] = make_float2(0.0f, 0.0f);

#pragma unroll 8
            for (int k = 0; k < CQK; k += 4) {
                float4 qv[2], kv[4];
#pragma unroll
                for (int ii = 0; ii < 2; ii++)
                    qv[ii] = *(float4*)&sQ[(ti + 32 * ii) * SQ_STR + k];
#pragma unroll
                for (int jj = 0; jj < 4; jj++)
                    kv[jj] = *(float4*)&sK[(tj + 16 * jj) * SQ_STR + k];
#pragma unroll
                for (int ii = 0; ii < 2; ii++) {
                    float2 qlo = make_float2(qv[ii].x, qv[ii].y);
                    float2 qhi = make_float2(qv[ii].z, qv[ii].w);
#pragma unroll
                    for (int jj = 0; jj < 4; jj++) {
                        ffma2(sacc[ii][jj], qlo, make_float2(kv[jj].x, kv[jj].y));
                        ffma2(sacc[ii][jj], qhi, make_float2(kv[jj].z, kv[jj].w));
                    }
                }
            }
#pragma unroll
            for (int ii = 0; ii < 2; ii++)
#pragma unroll
                for (int jj = 0; jj < 4; jj++)
                    sS[(ti + 32 * ii) * SS_STR + (tj + 16 * jj)] =
                        sacc[ii][jj].x + sacc[ii][jj].y;
        }
        __syncthreads();

        // ---- online softmax (base-2): 8 threads per row, 8 cols each ----
        {
            const int r  = tx >> 3;
            const int qq = tx & 7;
            float* row = &sS[r * SS_STR + qq * 8];
            float4 v0 = *(float4*)&row[0];
            float4 v1 = *(float4*)&row[4];
            float mx = fmaxf(fmaxf(fmaxf(v0.x, v0.y), fmaxf(v0.z, v0.w)),
                             fmaxf(fmaxf(v1.x, v1.y), fmaxf(v1.z, v1.w)));
            mx = fmaxf(mx, __shfl_xor_sync(0xffffffffu, mx, 1));
            mx = fmaxf(mx, __shfl_xor_sync(0xffffffffu, mx, 2));
            mx = fmaxf(mx, __shfl_xor_sync(0xffffffffu, mx, 4));
            float m_old = sM[r];
            float m_new = fmaxf(m_old, mx);
            v0.x = exp2_fast(v0.x - m_new);
            v0.y = exp2_fast(v0.y - m_new);
            v0.z = exp2_fast(v0.z - m_new);
            v0.w = exp2_fast(v0.w - m_new);
            v1.x = exp2_fast(v1.x - m_new);
            v1.y = exp2_fast(v1.y - m_new);
            v1.z = exp2_fast(v1.z - m_new);
            v1.w = exp2_fast(v1.w - m_new);
            float sum = ((v0.x + v0.y) + (v0.z + v0.w))
                      + ((v1.x + v1.y) + (v1.z + v1.w));
            *(float4*)&row[0] = v0;
            *(float4*)&row[4] = v1;
            sum += __shfl_xor_sync(0xffffffffu, sum, 1);
            sum += __shfl_xor_sync(0xffffffffu, sum, 2);
            sum += __shfl_xor_sync(0xffffffffu, sum, 4);
            if (qq == 0) {
                float scl = exp2_fast(m_old - m_new);
                sScale[r] = scl;
                sM[r] = m_new;
                sL[r] = sL[r] * scl + sum;
            }
        }
        __syncthreads();

        // ---- rescale accumulators, acc += P @ V (conflict-free V loads) ----
        {
#pragma unroll
            for (int ii = 0; ii < 2; ii++) {
                float s = sScale[ti + 32 * ii];
                float2 s2 = make_float2(s, s);
#pragma unroll
                for (int cc = 0; cc < 8; cc++) fmul2(acc[ii][cc], s2);
            }

#pragma unroll 4
            for (int j = 0; j < BJ; j++) {
                float2 pp[2];
#pragma unroll
                for (int ii = 0; ii < 2; ii++) {
                    float p = sS[(ti + 32 * ii) * SS_STR + j];
                    pp[ii] = make_float2(p, p);
                }
                const float* vrow = &sV[j * SV_STR + tj * 4];
                float4 v0 = *(const float4*)&vrow[0];
                float4 v1 = *(const float4*)&vrow[64];
                float4 v2 = *(const float4*)&vrow[128];
                float4 v3 = *(const float4*)&vrow[192];
                float2 vv[8] = {
                    make_float2(v0.x, v0.y), make_float2(v0.z, v0.w),
                    make_float2(v1.x, v1.y), make_float2(v1.z, v1.w),
                    make_float2(v2.x, v2.y), make_float2(v2.z, v2.w),
                    make_float2(v3.x, v3.y), make_float2(v3.z, v3.w)};
#pragma unroll
                for (int ii = 0; ii < 2; ii++)
#pragma unroll
                    for (int cc = 0; cc < 8; cc++)
                        ffma2(acc[ii][cc], pp[ii], vv[cc]);
            }
        }
        __syncthreads();
    }

    // ---- epilogue: normalize, transpose via smem, fused coalesced writes ----
    float rl[2];
#pragma unroll
    for (int ii = 0; ii < 2; ii++) rl[ii] = 1.0f / sL[ti + 32 * ii];

    float* sT = sV;  // overlay: needs 256*68 = 17408 floats; sM/sL at +20736 safe
#pragma unroll
    for (int ii = 0; ii < 2; ii++)
#pragma unroll
        for (int cc = 0; cc < 8; cc++) {
            int c = 64 * (cc >> 1) + tj * 4 + 2 * (cc & 1);
            sT[(c + 0) * (BI + 4) + (ti + 32 * ii)] = acc[ii][cc].x * rl[ii];
            sT[(c + 1) * (BI + 4) + (ti + 32 * ii)] = acc[ii][cc].y * rl[ii];
        }
    __syncthreads();

    float* attn_out = out + (size_t)BATCH * CV * NPIX;
    for (int t = tx; t < CV * BI / 4; t += NT) {
        int c  = t >> 4;
        int i4 = (t & 15) << 2;
        float4 v = *(float4*)&sT[c * (BI + 4) + i4];
        size_t g = ((size_t)b * CV + c) * NPIX + i0 + i4;
        float4 m = *(const float4*)&motion[g];
        float4 f;
        f.x = v.x * m.x; f.y = v.y * m.y; f.z = v.z * m.z; f.w = v.w * m.w;
        *(float4*)&out[g] = f;        // fuse_out
        *(float4*)&attn_out[g] = v;   // out
    }
}

// ============================================================================
extern "C" void kernel_launch(void* const* d_in, const int* in_sizes, int n_in,
                              void* d_out, int out_size)
{
    const float* a1  = (const float*)d_in[0];
    const float* a2  = (const float*)d_in[1];
    const float* mot = (const float*)d_in[2];
    const float* Wq  = (const float*)d_in[3];
    const float* bq  = (const float*)d_in[4];
    const float* Wk  = (const float*)d_in[5];
    const float* bk  = (const float*)d_in[6];
    const float* Wv  = (const float*)d_in[7];
    const float* bv  = (const float*)d_in[8];
    float* out = (float*)d_out;

    float *Qp, *Kp, *Vp;
    cudaGetSymbolAddress((void**)&Qp, g_Q);
    cudaGetSymbolAddress((void**)&Kp, g_K);
    cudaGetSymbolAddress((void**)&Vp, g_V);

    const float LOG2E = 1.4426950408889634f;

    proj_kernel<CQK, CQK><<<dim3(NPIX / 64, CQK / 64, BATCH), 256>>>(a2, Wq, bq, Qp, LOG2E);
    proj_kernel<CQK, CQK><<<dim3(NPIX / 64, CQK / 64, BATCH), 256>>>(a1, Wk, bk, Kp, 1.0f);
    proj_kernel<CV,  CV ><<<dim3(NPIX / 64, CV  / 64, BATCH), 256>>>(mot, Wv, bv, Vp, 1.0f);

    cudaFuncSetAttribute(flash_kernel, cudaFuncAttributeMaxDynamicSharedMemorySize, SMEM_BYTES);
    flash_kernel<<<dim3(NPIX / BI, BATCH), NT, SMEM_BYTES>>>(Qp, Kp, Vp, mot, out);
}

// round 10
// speedup vs baseline: 1.4267x; 1.4267x over previous
#include <cuda_runtime.h>
#include <cstdint>

#define BATCH 8
#define NPIX  4096
#define CQK   128
#define CV    256

// ---- scratch (device globals: no runtime allocation allowed) ----
__device__ float g_Q[BATCH * NPIX * CQK];   // [b][i][c], pre-scaled by log2(e)
__device__ float g_K[BATCH * NPIX * CQK];   // [b][j][c]
__device__ float g_V[BATCH * NPIX * CV];    // [b][j][c]

// ============================================================================
// packed f32x2 FMA/MUL (sm_103a): 2 fp32 MACs per issue slot.
// ============================================================================
__device__ __forceinline__ void ffma2(float2& d, const float2 a, const float2 b) {
    asm("fma.rn.f32x2 %0, %1, %2, %0;"
        : "+l"(reinterpret_cast<unsigned long long&>(d))
        : "l"(reinterpret_cast<const unsigned long long&>(a)),
          "l"(reinterpret_cast<const unsigned long long&>(b)));
}
__device__ __forceinline__ void fmul2(float2& d, const float2 a) {
    asm("mul.rn.f32x2 %0, %0, %1;"
        : "+l"(reinterpret_cast<unsigned long long&>(d))
        : "l"(reinterpret_cast<const unsigned long long&>(a)));
}

// ============================================================================
// fast exp2 on the FMA pipe
// ============================================================================
__device__ __forceinline__ float exp2_fast(float x) {
    x = fmaxf(x, -126.0f);
    float fl = floorf(x);
    float f  = x - fl;
    float p  = 1.87757667e-3f;
    p = fmaf(p, f, 8.98934058e-3f);
    p = fmaf(p, f, 5.58263180e-2f);
    p = fmaf(p, f, 2.40153617e-1f);
    p = fmaf(p, f, 6.93153073e-1f);
    p = fmaf(p, f, 9.99999994e-1f);
    int e = (int)fl;
    float sc = __int_as_float((e + 127) << 23);
    return p * sc;
}

// ============================================================================
// Projection GEMM: out[b][i][o] = sum_k W[o][k] * in[b][k][i] + bias[o], *scale
// ============================================================================
template<int CIN, int COUT>
__global__ __launch_bounds__(256) void proj_kernel(
    const float* __restrict__ in, const float* __restrict__ W,
    const float* __restrict__ bias, float* __restrict__ out, float scale)
{
    __shared__ float sIn[32][64];   // [k][i]
    __shared__ float sWT[32][64];   // [k][o]
    __shared__ float sOut[64][64];  // [i][o]

    const int b  = blockIdx.z;
    const int i0 = blockIdx.x * 64;
    const int o0 = blockIdx.y * 64;
    const int tx = threadIdx.x;
    const int ti = tx & 15;
    const int to = tx >> 4;

    const float* inb = in + (size_t)b * CIN * NPIX + i0;

    float acc[4][4];
#pragma unroll
    for (int a = 0; a < 4; a++)
#pragma unroll
        for (int c = 0; c < 4; c++) acc[a][c] = 0.0f;

    for (int k0 = 0; k0 < CIN; k0 += 32) {
        for (int t = tx; t < 32 * 64 / 4; t += 256) {
            int k  = t >> 4;
            int i4 = (t & 15) << 2;
            *(float4*)&sIn[k][i4] = *(const float4*)&inb[(size_t)(k0 + k) * NPIX + i4];
        }
        for (int t = tx; t < 64 * 32 / 4; t += 256) {
            int o  = t >> 3;
            int k4 = (t & 7) << 2;
            float4 w = *(const float4*)&W[(size_t)(o0 + o) * CIN + k0 + k4];
            sWT[k4 + 0][o] = w.x; sWT[k4 + 1][o] = w.y;
            sWT[k4 + 2][o] = w.z; sWT[k4 + 3][o] = w.w;
        }
        __syncthreads();
#pragma unroll
        for (int k = 0; k < 32; k++) {
            float4 a = *(float4*)&sIn[k][ti * 4];
            float4 w = *(float4*)&sWT[k][to * 4];
            float av[4] = {a.x, a.y, a.z, a.w};
            float wv[4] = {w.x, w.y, w.z, w.w};
#pragma unroll
            for (int ii = 0; ii < 4; ii++)
#pragma unroll
                for (int oo = 0; oo < 4; oo++)
                    acc[ii][oo] = fmaf(av[ii], wv[oo], acc[ii][oo]);
        }
        __syncthreads();
    }

#pragma unroll
    for (int ii = 0; ii < 4; ii++)
#pragma unroll
        for (int oo = 0; oo < 4; oo++)
            sOut[ti * 4 + ii][to * 4 + oo] = acc[ii][oo];
    __syncthreads();

    for (int t = tx; t < 64 * 64 / 4; t += 256) {
        int i  = t >> 4;
        int o4 = (t & 15) << 2;
        float4 v = *(float4*)&sOut[i][o4];
        float4 bb = *(const float4*)&bias[o0 + o4];
        v.x = (v.x + bb.x) * scale;
        v.y = (v.y + bb.y) * scale;
        v.z = (v.z + bb.z) * scale;
        v.w = (v.w + bb.w) * scale;
        *(float4*)&out[((size_t)b * NPIX + i0 + i) * COUT + o0 + o4] = v;
    }
}

// ============================================================================
// Flash attention + fuse — 256 threads, 4x4 QK micro-tile (R5 shape).
//   PV warp-c-specialization: warp w owns c in [32w, 32w+32); lane l:
//     ig = l>>1 -> i = ig + 16*ii (ii 0..3), ch = l&1 -> c0 = 32w + 16ch.
//   Per j per warp: V = 4 LDS.128 x 1 wf (2 distinct addrs), p loaded as
//   float4 per j-quad (2 wf each) -> 6 wf/j vs 12 in the old mapping.
// ============================================================================
#define BI 64
#define BJ 64
#define NT 256
#define SQ_STR 132   // 128 + 4 pad
#define SV_STR 256
#define SS_STR 68    // 64 + 4 pad (multiple of 4: float4 row loads stay aligned)

#define SMEM_FLOATS (BI*SQ_STR + BJ*SQ_STR + BJ*SV_STR + BI*SS_STR + 3*BI)
#define SMEM_BYTES  (SMEM_FLOATS * 4)

__global__ __launch_bounds__(NT, 1) void flash_kernel(
    const float* __restrict__ Q, const float* __restrict__ K,
    const float* __restrict__ V, const float* __restrict__ motion,
    float* __restrict__ out)
{
    extern __shared__ float smem[];
    float* sQ = smem;                      // [BI][SQ_STR]
    float* sK = sQ + BI * SQ_STR;          // [BJ][SQ_STR]
    float* sV = sK + BJ * SQ_STR;          // [BJ][SV_STR]
    float* sS = sV + BJ * SV_STR;          // [BI][SS_STR]
    float* sM = sS + BI * SS_STR;
    float* sL = sM + BI;
    float* sScale = sL + BI;

    const int b  = blockIdx.y;
    const int i0 = blockIdx.x * BI;
    const int tx = threadIdx.x;
    // QK-phase mapping
    const int ti = tx >> 4;    // 0..15
    const int tj = tx & 15;    // 0..15
    // PV-phase mapping (warp-c specialization)
    const int w  = tx >> 5;    // warp 0..7
    const int l  = tx & 31;
    const int ig = l >> 1;     // 0..15 : i = ig + 16*ii
    const int c0 = 32 * w + 16 * (l & 1);  // base channel of this thread's 16-c block

    const float* Qb = Q + ((size_t)b * NPIX + i0) * CQK;
    const float* Kb = K + (size_t)b * NPIX * CQK;
    const float* Vb = V + (size_t)b * NPIX * CV;

    // load Q tile once
    for (int t = tx; t < BI * CQK / 4; t += NT) {
        int i  = t >> 5;
        int k4 = (t & 31) << 2;
        *(float4*)&sQ[i * SQ_STR + k4] = *(const float4*)&Qb[(size_t)i * CQK + k4];
    }
    if (tx < BI) { sM[tx] = -1e30f; sL[tx] = 0.0f; }

    // PV accumulators: i = ig + 16*ii ; c = c0 + 2*cc2 + {0,1}
    float2 acc[4][8];
#pragma unroll
    for (int ii = 0; ii < 4; ii++)
#pragma unroll
        for (int cc = 0; cc < 8; cc++) acc[ii][cc] = make_float2(0.0f, 0.0f);

    for (int j0 = 0; j0 < NPIX; j0 += BJ) {
        // ---- load K, V tiles ----
        for (int t = tx; t < BJ * CQK / 4; t += NT) {
            int j  = t >> 5;
            int k4 = (t & 31) << 2;
            *(float4*)&sK[j * SQ_STR + k4] = *(const float4*)&Kb[(size_t)(j0 + j) * CQK + k4];
        }
        for (int t = tx; t < BJ * CV / 4; t += NT) {
            int j  = t >> 6;
            int c4 = (t & 63) << 2;
            *(float4*)&sV[j * SV_STR + c4] = *(const float4*)&Vb[(size_t)(j0 + j) * CV + c4];
        }
        __syncthreads();

        // ---- S = Q Kt : 4x4 micro-tile, float2 accumulators along k ----
        {
            float2 sacc[4][4];
#pragma unroll
            for (int a = 0; a < 4; a++)
#pragma unroll
                for (int c = 0; c < 4; c++) sacc[a][c] = make_float2(0.0f, 0.0f);

#pragma unroll 8
            for (int k = 0; k < CQK; k += 4) {
                float4 qv[4], kv[4];
#pragma unroll
                for (int ii = 0; ii < 4; ii++)
                    qv[ii] = *(float4*)&sQ[(ti + 16 * ii) * SQ_STR + k];
#pragma unroll
                for (int jj = 0; jj < 4; jj++)
                    kv[jj] = *(float4*)&sK[(tj + 16 * jj) * SQ_STR + k];
#pragma unroll
                for (int ii = 0; ii < 4; ii++) {
                    float2 qlo = make_float2(qv[ii].x, qv[ii].y);
                    float2 qhi = make_float2(qv[ii].z, qv[ii].w);
#pragma unroll
                    for (int jj = 0; jj < 4; jj++) {
                        ffma2(sacc[ii][jj], qlo, make_float2(kv[jj].x, kv[jj].y));
                        ffma2(sacc[ii][jj], qhi, make_float2(kv[jj].z, kv[jj].w));
                    }
                }
            }
#pragma unroll
            for (int ii = 0; ii < 4; ii++)
#pragma unroll
                for (int jj = 0; jj < 4; jj++)
                    sS[(ti + 16 * ii) * SS_STR + (tj + 16 * jj)] =
                        sacc[ii][jj].x + sacc[ii][jj].y;
        }
        __syncthreads();

        // ---- online softmax (base-2): 4 threads per row, 16 cols each ----
        {
            const int r  = tx >> 2;
            const int qq = tx & 3;
            float* row = &sS[r * SS_STR + qq * 16];
            float mx = -1e30f;
#pragma unroll
            for (int t = 0; t < 16; t += 4) {
                float4 v = *(float4*)&row[t];
                mx = fmaxf(mx, fmaxf(fmaxf(v.x, v.y), fmaxf(v.z, v.w)));
            }
            mx = fmaxf(mx, __shfl_xor_sync(0xffffffffu, mx, 1));
            mx = fmaxf(mx, __shfl_xor_sync(0xffffffffu, mx, 2));
            float m_old = sM[r];
            float m_new = fmaxf(m_old, mx);
            float sum = 0.0f;
#pragma unroll
            for (int t = 0; t < 16; t += 4) {
                float4 v = *(float4*)&row[t];
                v.x = exp2_fast(v.x - m_new);
                v.y = exp2_fast(v.y - m_new);
                v.z = exp2_fast(v.z - m_new);
                v.w = exp2_fast(v.w - m_new);
                sum += (v.x + v.y) + (v.z + v.w);
                *(float4*)&row[t] = v;
            }
            sum += __shfl_xor_sync(0xffffffffu, sum, 1);
            sum += __shfl_xor_sync(0xffffffffu, sum, 2);
            if (qq == 0) {
                float scl = exp2_fast(m_old - m_new);
                sScale[r] = scl;
                sM[r] = m_new;
                sL[r] = sL[r] * scl + sum;
            }
        }
        __syncthreads();

        // ---- rescale accumulators, acc += P @ V (warp-c specialization) ----
        {
#pragma unroll
            for (int ii = 0; ii < 4; ii++) {
                float s = sScale[ig + 16 * ii];
                float2 s2 = make_float2(s, s);
#pragma unroll
                for (int cc = 0; cc < 8; cc++) fmul2(acc[ii][cc], s2);
            }

            for (int j = 0; j < BJ; j += 4) {
                // p for 4 j's at once: float4 per i-row (2 wf per load, optimal)
                float4 p4[4];
#pragma unroll
                for (int ii = 0; ii < 4; ii++)
                    p4[ii] = *(float4*)&sS[(ig + 16 * ii) * SS_STR + j];
#pragma unroll
                for (int e = 0; e < 4; e++) {
                    const float* vrow = &sV[(j + e) * SV_STR + c0];
                    float4 v0 = *(const float4*)&vrow[0];
                    float4 v1 = *(const float4*)&vrow[4];
                    float4 v2 = *(const float4*)&vrow[8];
                    float4 v3 = *(const float4*)&vrow[12];
                    float2 vv[8] = {
                        make_float2(v0.x, v0.y), make_float2(v0.z, v0.w),
                        make_float2(v1.x, v1.y), make_float2(v1.z, v1.w),
                        make_float2(v2.x, v2.y), make_float2(v2.z, v2.w),
                        make_float2(v3.x, v3.y), make_float2(v3.z, v3.w)};
#pragma unroll
                    for (int ii = 0; ii < 4; ii++) {
                        float pe = (e == 0) ? p4[ii].x : (e == 1) ? p4[ii].y
                                 : (e == 2) ? p4[ii].z : p4[ii].w;
                        float2 pp = make_float2(pe, pe);
#pragma unroll
                        for (int cc = 0; cc < 8; cc++)
                            ffma2(acc[ii][cc], pp, vv[cc]);
                    }
                }
            }
        }
        __syncthreads();
    }

    // ---- epilogue: normalize, transpose via smem, fused coalesced writes ----
    float rl[4];
#pragma unroll
    for (int ii = 0; ii < 4; ii++) rl[ii] = 1.0f / sL[ig + 16 * ii];

    float* sT = sV;  // overlay: needs 256*68 = 17408 floats; sM/sL at +20736 safe
#pragma unroll
    for (int ii = 0; ii < 4; ii++)
#pragma unroll
        for (int cc = 0; cc < 8; cc++) {
            int c = c0 + 2 * cc;
            sT[(c + 0) * (BI + 4) + (ig + 16 * ii)] = acc[ii][cc].x * rl[ii];
            sT[(c + 1) * (BI + 4) + (ig + 16 * ii)] = acc[ii][cc].y * rl[ii];
        }
    __syncthreads();

    float* attn_out = out + (size_t)BATCH * CV * NPIX;
    for (int t = tx; t < CV * BI / 4; t += NT) {
        int c  = t >> 4;
        int i4 = (t & 15) << 2;
        float4 v = *(float4*)&sT[c * (BI + 4) + i4];
        size_t g = ((size_t)b * CV + c) * NPIX + i0 + i4;
        float4 m = *(const float4*)&motion[g];
        float4 f;
        f.x = v.x * m.x; f.y = v.y * m.y; f.z = v.z * m.z; f.w = v.w * m.w;
        *(float4*)&out[g] = f;        // fuse_out
        *(float4*)&attn_out[g] = v;   // out
    }
}

// ============================================================================
extern "C" void kernel_launch(void* const* d_in, const int* in_sizes, int n_in,
                              void* d_out, int out_size)
{
    const float* a1  = (const float*)d_in[0];
    const float* a2  = (const float*)d_in[1];
    const float* mot = (const float*)d_in[2];
    const float* Wq  = (const float*)d_in[3];
    const float* bq  = (const float*)d_in[4];
    const float* Wk  = (const float*)d_in[5];
    const float* bk  = (const float*)d_in[6];
    const float* Wv  = (const float*)d_in[7];
    const float* bv  = (const float*)d_in[8];
    float* out = (float*)d_out;

    float *Qp, *Kp, *Vp;
    cudaGetSymbolAddress((void**)&Qp, g_Q);
    cudaGetSymbolAddress((void**)&Kp, g_K);
    cudaGetSymbolAddress((void**)&Vp, g_V);

    const float LOG2E = 1.4426950408889634f;

    proj_kernel<CQK, CQK><<<dim3(NPIX / 64, CQK / 64, BATCH), 256>>>(a2, Wq, bq, Qp, LOG2E);
    proj_kernel<CQK, CQK><<<dim3(NPIX / 64, CQK / 64, BATCH), 256>>>(a1, Wk, bk, Kp, 1.0f);
    proj_kernel<CV,  CV ><<<dim3(NPIX / 64, CV  / 64, BATCH), 256>>>(mot, Wv, bv, Vp, 1.0f);

    cudaFuncSetAttribute(flash_kernel, cudaFuncAttributeMaxDynamicSharedMemorySize, SMEM_BYTES);
    flash_kernel<<<dim3(NPIX / BI, BATCH), NT, SMEM_BYTES>>>(Qp, Kp, Vp, mot, out);
}

// round 11
// speedup vs baseline: 1.4739x; 1.0331x over previous
#include <cuda_runtime.h>
#include <cstdint>

#define BATCH 8
#define NPIX  4096
#define CQK   128
#define CV    256

// ---- scratch (device globals: no runtime allocation allowed) ----
__device__ float g_Q[BATCH * NPIX * CQK];   // [b][i][c], pre-scaled by log2(e)
__device__ float g_K[BATCH * NPIX * CQK];   // [b][j][c]
__device__ float g_V[BATCH * NPIX * CV];    // [b][j][c]

// ============================================================================
// packed f32x2 FMA/MUL (sm_103a): 2 fp32 MACs per issue slot.
// ============================================================================
__device__ __forceinline__ void ffma2(float2& d, const float2 a, const float2 b) {
    asm("fma.rn.f32x2 %0, %1, %2, %0;"
        : "+l"(reinterpret_cast<unsigned long long&>(d))
        : "l"(reinterpret_cast<const unsigned long long&>(a)),
          "l"(reinterpret_cast<const unsigned long long&>(b)));
}
__device__ __forceinline__ void fmul2(float2& d, const float2 a) {
    asm("mul.rn.f32x2 %0, %0, %1;"
        : "+l"(reinterpret_cast<unsigned long long&>(d))
        : "l"(reinterpret_cast<const unsigned long long&>(a)));
}

// ============================================================================
// fast exp2 on the FMA pipe
// ============================================================================
__device__ __forceinline__ float exp2_fast(float x) {
    x = fmaxf(x, -126.0f);
    float fl = floorf(x);
    float f  = x - fl;
    float p  = 1.87757667e-3f;
    p = fmaf(p, f, 8.98934058e-3f);
    p = fmaf(p, f, 5.58263180e-2f);
    p = fmaf(p, f, 2.40153617e-1f);
    p = fmaf(p, f, 6.93153073e-1f);
    p = fmaf(p, f, 9.99999994e-1f);
    int e = (int)fl;
    float sc = __int_as_float((e + 127) << 23);
    return p * sc;
}

// ============================================================================
// Projection GEMM: out[b][i][o] = sum_k W[o][k] * in[b][k][i] + bias[o], *scale
// ============================================================================
template<int CIN, int COUT>
__global__ __launch_bounds__(256) void proj_kernel(
    const float* __restrict__ in, const float* __restrict__ W,
    const float* __restrict__ bias, float* __restrict__ out, float scale)
{
    __shared__ float sIn[32][64];   // [k][i]
    __shared__ float sWT[32][64];   // [k][o]
    __shared__ float sOut[64][64];  // [i][o]

    const int b  = blockIdx.z;
    const int i0 = blockIdx.x * 64;
    const int o0 = blockIdx.y * 64;
    const int tx = threadIdx.x;
    const int ti = tx & 15;
    const int to = tx >> 4;

    const float* inb = in + (size_t)b * CIN * NPIX + i0;

    float acc[4][4];
#pragma unroll
    for (int a = 0; a < 4; a++)
#pragma unroll
        for (int c = 0; c < 4; c++) acc[a][c] = 0.0f;

    for (int k0 = 0; k0 < CIN; k0 += 32) {
        for (int t = tx; t < 32 * 64 / 4; t += 256) {
            int k  = t >> 4;
            int i4 = (t & 15) << 2;
            *(float4*)&sIn[k][i4] = *(const float4*)&inb[(size_t)(k0 + k) * NPIX + i4];
        }
        for (int t = tx; t < 64 * 32 / 4; t += 256) {
            int o  = t >> 3;
            int k4 = (t & 7) << 2;
            float4 w = *(const float4*)&W[(size_t)(o0 + o) * CIN + k0 + k4];
            sWT[k4 + 0][o] = w.x; sWT[k4 + 1][o] = w.y;
            sWT[k4 + 2][o] = w.z; sWT[k4 + 3][o] = w.w;
        }
        __syncthreads();
#pragma unroll
        for (int k = 0; k < 32; k++) {
            float4 a = *(float4*)&sIn[k][ti * 4];
            float4 w = *(float4*)&sWT[k][to * 4];
            float av[4] = {a.x, a.y, a.z, a.w};
            float wv[4] = {w.x, w.y, w.z, w.w};
#pragma unroll
            for (int ii = 0; ii < 4; ii++)
#pragma unroll
                for (int oo = 0; oo < 4; oo++)
                    acc[ii][oo] = fmaf(av[ii], wv[oo], acc[ii][oo]);
        }
        __syncthreads();
    }

#pragma unroll
    for (int ii = 0; ii < 4; ii++)
#pragma unroll
        for (int oo = 0; oo < 4; oo++)
            sOut[ti * 4 + ii][to * 4 + oo] = acc[ii][oo];
    __syncthreads();

    for (int t = tx; t < 64 * 64 / 4; t += 256) {
        int i  = t >> 4;
        int o4 = (t & 15) << 2;
        float4 v = *(float4*)&sOut[i][o4];
        float4 bb = *(const float4*)&bias[o0 + o4];
        v.x = (v.x + bb.x) * scale;
        v.y = (v.y + bb.y) * scale;
        v.z = (v.z + bb.z) * scale;
        v.w = (v.w + bb.w) * scale;
        *(float4*)&out[((size_t)b * NPIX + i0 + i) * COUT + o0 + o4] = v;
    }
}

// ============================================================================
// Flash attention + fuse — BJ=32 for 2 CTAs/SM (93.4 KB smem each).
//   QK micro-tile 4x2 (i = ti+16*ii, j = tj+16*jj, jj 0..1).
//   PV warp-c specialization: warp w owns c in [32w,32w+32);
//     lane l: ig = l>>1, c0 = 32w + 16*(l&1). Conflict-free V loads.
// ============================================================================
#define BI 64
#define BJ 32
#define NT 256
#define SQ_STR 132   // 128 + 4 pad
#define SV_STR 256
#define SS_STR 36    // 32 + 4 pad

#define SMEM_FLOATS (BI*SQ_STR + BJ*SQ_STR + BJ*SV_STR + BI*SS_STR + 3*BI)
#define SMEM_BYTES  (SMEM_FLOATS * 4)

__global__ __launch_bounds__(NT, 2) void flash_kernel(
    const float* __restrict__ Q, const float* __restrict__ K,
    const float* __restrict__ V, const float* __restrict__ motion,
    float* __restrict__ out)
{
    extern __shared__ float smem[];
    float* sQ = smem;                      // [BI][SQ_STR]
    float* sK = sQ + BI * SQ_STR;          // [BJ][SQ_STR]
    float* sV = sK + BJ * SQ_STR;          // [BJ][SV_STR]
    float* sS = sV + BJ * SV_STR;          // [BI][SS_STR]
    float* sM = sS + BI * SS_STR;
    float* sL = sM + BI;
    float* sScale = sL + BI;

    const int b  = blockIdx.y;
    const int i0 = blockIdx.x * BI;
    const int tx = threadIdx.x;
    // QK-phase mapping
    const int ti = tx >> 4;    // 0..15
    const int tj = tx & 15;    // 0..15
    // PV-phase mapping (warp-c specialization)
    const int w  = tx >> 5;    // warp 0..7
    const int l  = tx & 31;
    const int ig = l >> 1;     // 0..15 : i = ig + 16*ii
    const int c0 = 32 * w + 16 * (l & 1);

    const float* Qb = Q + ((size_t)b * NPIX + i0) * CQK;
    const float* Kb = K + (size_t)b * NPIX * CQK;
    const float* Vb = V + (size_t)b * NPIX * CV;

    // load Q tile once
    for (int t = tx; t < BI * CQK / 4; t += NT) {
        int i  = t >> 5;
        int k4 = (t & 31) << 2;
        *(float4*)&sQ[i * SQ_STR + k4] = *(const float4*)&Qb[(size_t)i * CQK + k4];
    }
    if (tx < BI) { sM[tx] = -1e30f; sL[tx] = 0.0f; }

    // PV accumulators: i = ig + 16*ii ; c = c0 + 2*cc + {0,1}
    float2 acc[4][8];
#pragma unroll
    for (int ii = 0; ii < 4; ii++)
#pragma unroll
        for (int cc = 0; cc < 8; cc++) acc[ii][cc] = make_float2(0.0f, 0.0f);

    for (int j0 = 0; j0 < NPIX; j0 += BJ) {
        // ---- load K, V tiles ----
        for (int t = tx; t < BJ * CQK / 4; t += NT) {
            int j  = t >> 5;
            int k4 = (t & 31) << 2;
            *(float4*)&sK[j * SQ_STR + k4] = *(const float4*)&Kb[(size_t)(j0 + j) * CQK + k4];
        }
        for (int t = tx; t < BJ * CV / 4; t += NT) {
            int j  = t >> 6;
            int c4 = (t & 63) << 2;
            *(float4*)&sV[j * SV_STR + c4] = *(const float4*)&Vb[(size_t)(j0 + j) * CV + c4];
        }
        __syncthreads();

        // ---- S = Q Kt : 4x2 micro-tile, float2 accumulators along k ----
        {
            float2 sacc[4][2];
#pragma unroll
            for (int a = 0; a < 4; a++)
#pragma unroll
                for (int c = 0; c < 2; c++) sacc[a][c] = make_float2(0.0f, 0.0f);

#pragma unroll 8
            for (int k = 0; k < CQK; k += 4) {
                float4 qv[4], kv[2];
#pragma unroll
                for (int ii = 0; ii < 4; ii++)
                    qv[ii] = *(float4*)&sQ[(ti + 16 * ii) * SQ_STR + k];
#pragma unroll
                for (int jj = 0; jj < 2; jj++)
                    kv[jj] = *(float4*)&sK[(tj + 16 * jj) * SQ_STR + k];
#pragma unroll
                for (int ii = 0; ii < 4; ii++) {
                    float2 qlo = make_float2(qv[ii].x, qv[ii].y);
                    float2 qhi = make_float2(qv[ii].z, qv[ii].w);
#pragma unroll
                    for (int jj = 0; jj < 2; jj++) {
                        ffma2(sacc[ii][jj], qlo, make_float2(kv[jj].x, kv[jj].y));
                        ffma2(sacc[ii][jj], qhi, make_float2(kv[jj].z, kv[jj].w));
                    }
                }
            }
#pragma unroll
            for (int ii = 0; ii < 4; ii++)
#pragma unroll
                for (int jj = 0; jj < 2; jj++)
                    sS[(ti + 16 * ii) * SS_STR + (tj + 16 * jj)] =
                        sacc[ii][jj].x + sacc[ii][jj].y;
        }
        __syncthreads();

        // ---- online softmax (base-2): 4 threads per row, 8 cols each ----
        {
            const int r  = tx >> 2;
            const int qq = tx & 3;
            float* row = &sS[r * SS_STR + qq * 8];
            float4 v0 = *(float4*)&row[0];
            float4 v1 = *(float4*)&row[4];
            float mx = fmaxf(fmaxf(fmaxf(v0.x, v0.y), fmaxf(v0.z, v0.w)),
                             fmaxf(fmaxf(v1.x, v1.y), fmaxf(v1.z, v1.w)));
            mx = fmaxf(mx, __shfl_xor_sync(0xffffffffu, mx, 1));
            mx = fmaxf(mx, __shfl_xor_sync(0xffffffffu, mx, 2));
            float m_old = sM[r];
            float m_new = fmaxf(m_old, mx);
            v0.x = exp2_fast(v0.x - m_new);
            v0.y = exp2_fast(v0.y - m_new);
            v0.z = exp2_fast(v0.z - m_new);
            v0.w = exp2_fast(v0.w - m_new);
            v1.x = exp2_fast(v1.x - m_new);
            v1.y = exp2_fast(v1.y - m_new);
            v1.z = exp2_fast(v1.z - m_new);
            v1.w = exp2_fast(v1.w - m_new);
            float sum = ((v0.x + v0.y) + (v0.z + v0.w))
                      + ((v1.x + v1.y) + (v1.z + v1.w));
            *(float4*)&row[0] = v0;
            *(float4*)&row[4] = v1;
            sum += __shfl_xor_sync(0xffffffffu, sum, 1);
            sum += __shfl_xor_sync(0xffffffffu, sum, 2);
            if (qq == 0) {
                float scl = exp2_fast(m_old - m_new);
                sScale[r] = scl;
                sM[r] = m_new;
                sL[r] = sL[r] * scl + sum;
            }
        }
        __syncthreads();

        // ---- rescale accumulators, acc += P @ V (warp-c specialization) ----
        {
#pragma unroll
            for (int ii = 0; ii < 4; ii++) {
                float s = sScale[ig + 16 * ii];
                float2 s2 = make_float2(s, s);
#pragma unroll
                for (int cc = 0; cc < 8; cc++) fmul2(acc[ii][cc], s2);
            }

#pragma unroll
            for (int j = 0; j < BJ; j += 4) {
                float4 p4[4];
#pragma unroll
                for (int ii = 0; ii < 4; ii++)
                    p4[ii] = *(float4*)&sS[(ig + 16 * ii) * SS_STR + j];
#pragma unroll
                for (int e = 0; e < 4; e++) {
                    const float* vrow = &sV[(j + e) * SV_STR + c0];
                    float4 v0 = *(const float4*)&vrow[0];
                    float4 v1 = *(const float4*)&vrow[4];
                    float4 v2 = *(const float4*)&vrow[8];
                    float4 v3 = *(const float4*)&vrow[12];
                    float2 vv[8] = {
                        make_float2(v0.x, v0.y), make_float2(v0.z, v0.w),
                        make_float2(v1.x, v1.y), make_float2(v1.z, v1.w),
                        make_float2(v2.x, v2.y), make_float2(v2.z, v2.w),
                        make_float2(v3.x, v3.y), make_float2(v3.z, v3.w)};
#pragma unroll
                    for (int ii = 0; ii < 4; ii++) {
                        float pe = (e == 0) ? p4[ii].x : (e == 1) ? p4[ii].y
                                 : (e == 2) ? p4[ii].z : p4[ii].w;
                        float2 pp = make_float2(pe, pe);
#pragma unroll
                        for (int cc = 0; cc < 8; cc++)
                            ffma2(acc[ii][cc], pp, vv[cc]);
                    }
                }
            }
        }
        __syncthreads();
    }

    // ---- epilogue: normalize, transpose via smem, fused coalesced writes ----
    float rl[4];
#pragma unroll
    for (int ii = 0; ii < 4; ii++) rl[ii] = 1.0f / sL[ig + 16 * ii];

    // overlay at smem base: needs 256*68 = 17408 floats; sM/sL live at
    // offset 23168+ and are read into rl before any write below. The last
    // tile iteration ended with __syncthreads(), so sS reads are ordered.
    float* sT = smem;
#pragma unroll
    for (int ii = 0; ii < 4; ii++)
#pragma unroll
        for (int cc = 0; cc < 8; cc++) {
            int c = c0 + 2 * cc;
            sT[(c + 0) * (BI + 4) + (ig + 16 * ii)] = acc[ii][cc].x * rl[ii];
            sT[(c + 1) * (BI + 4) + (ig + 16 * ii)] = acc[ii][cc].y * rl[ii];
        }
    __syncthreads();

    float* attn_out = out + (size_t)BATCH * CV * NPIX;
    for (int t = tx; t < CV * BI / 4; t += NT) {
        int c  = t >> 4;
        int i4 = (t & 15) << 2;
        float4 v = *(float4*)&sT[c * (BI + 4) + i4];
        size_t g = ((size_t)b * CV + c) * NPIX + i0 + i4;
        float4 m = *(const float4*)&motion[g];
        float4 f;
        f.x = v.x * m.x; f.y = v.y * m.y; f.z = v.z * m.z; f.w = v.w * m.w;
        *(float4*)&out[g] = f;        // fuse_out
        *(float4*)&attn_out[g] = v;   // out
    }
}

// ============================================================================
extern "C" void kernel_launch(void* const* d_in, const int* in_sizes, int n_in,
                              void* d_out, int out_size)
{
    const float* a1  = (const float*)d_in[0];
    const float* a2  = (const float*)d_in[1];
    const float* mot = (const float*)d_in[2];
    const float* Wq  = (const float*)d_in[3];
    const float* bq  = (const float*)d_in[4];
    const float* Wk  = (const float*)d_in[5];
    const float* bk  = (const float*)d_in[6];
    const float* Wv  = (const float*)d_in[7];
    const float* bv  = (const float*)d_in[8];
    float* out = (float*)d_out;

    float *Qp, *Kp, *Vp;
    cudaGetSymbolAddress((void**)&Qp, g_Q);
    cudaGetSymbolAddress((void**)&Kp, g_K);
    cudaGetSymbolAddress((void**)&Vp, g_V);

    const float LOG2E = 1.4426950408889634f;

    proj_kernel<CQK, CQK><<<dim3(NPIX / 64, CQK / 64, BATCH), 256>>>(a2, Wq, bq, Qp, LOG2E);
    proj_kernel<CQK, CQK><<<dim3(NPIX / 64, CQK / 64, BATCH), 256>>>(a1, Wk, bk, Kp, 1.0f);
    proj_kernel<CV,  CV ><<<dim3(NPIX / 64, CV  / 64, BATCH), 256>>>(mot, Wv, bv, Vp, 1.0f);

    cudaFuncSetAttribute(flash_kernel, cudaFuncAttributeMaxDynamicSharedMemorySize, SMEM_BYTES);
    flash_kernel<<<dim3(NPIX / BI, BATCH), NT, SMEM_BYTES>>>(Qp, Kp, Vp, mot, out);
}

// round 12
// speedup vs baseline: 1.4768x; 1.0020x over previous
#include <cuda_runtime.h>
#include <cstdint>

#define BATCH 8
#define NPIX  4096
#define CQK   128
#define CV    256

// ---- scratch (device globals: no runtime allocation allowed) ----
__device__ float g_Q[BATCH * NPIX * CQK];   // [b][i][c], pre-scaled by log2(e)
__device__ float g_K[BATCH * NPIX * CQK];   // [b][j][c]
__device__ float g_V[BATCH * NPIX * CV];    // [b][j][c]

// ============================================================================
// packed f32x2 FMA/MUL (sm_103a): 2 fp32 MACs per issue slot.
// ============================================================================
__device__ __forceinline__ void ffma2(float2& d, const float2 a, const float2 b) {
    asm("fma.rn.f32x2 %0, %1, %2, %0;"
        : "+l"(reinterpret_cast<unsigned long long&>(d))
        : "l"(reinterpret_cast<const unsigned long long&>(a)),
          "l"(reinterpret_cast<const unsigned long long&>(b)));
}
__device__ __forceinline__ void fmul2(float2& d, const float2 a) {
    asm("mul.rn.f32x2 %0, %0, %1;"
        : "+l"(reinterpret_cast<unsigned long long&>(d))
        : "l"(reinterpret_cast<const unsigned long long&>(a)));
}

// ============================================================================
// fast exp2 on the FMA pipe
// ============================================================================
__device__ __forceinline__ float exp2_fast(float x) {
    x = fmaxf(x, -126.0f);
    float fl = floorf(x);
    float f  = x - fl;
    float p  = 1.87757667e-3f;
    p = fmaf(p, f, 8.98934058e-3f);
    p = fmaf(p, f, 5.58263180e-2f);
    p = fmaf(p, f, 2.40153617e-1f);
    p = fmaf(p, f, 6.93153073e-1f);
    p = fmaf(p, f, 9.99999994e-1f);
    int e = (int)fl;
    float sc = __int_as_float((e + 127) << 23);
    return p * sc;
}

// ============================================================================
// Projection GEMM: out[b][i][o] = sum_k W[o][k] * in[b][k][i] + bias[o], *scale
// ============================================================================
template<int CIN, int COUT>
__global__ __launch_bounds__(256) void proj_kernel(
    const float* __restrict__ in, const float* __restrict__ W,
    const float* __restrict__ bias, float* __restrict__ out, float scale)
{
    __shared__ float sIn[32][64];   // [k][i]
    __shared__ float sWT[32][64];   // [k][o]
    __shared__ float sOut[64][64];  // [i][o]

    const int b  = blockIdx.z;
    const int i0 = blockIdx.x * 64;
    const int o0 = blockIdx.y * 64;
    const int tx = threadIdx.x;
    const int ti = tx & 15;
    const int to = tx >> 4;

    const float* inb = in + (size_t)b * CIN * NPIX + i0;

    float acc[4][4];
#pragma unroll
    for (int a = 0; a < 4; a++)
#pragma unroll
        for (int c = 0; c < 4; c++) acc[a][c] = 0.0f;

    for (int k0 = 0; k0 < CIN; k0 += 32) {
        for (int t = tx; t < 32 * 64 / 4; t += 256) {
            int k  = t >> 4;
            int i4 = (t & 15) << 2;
            *(float4*)&sIn[k][i4] = *(const float4*)&inb[(size_t)(k0 + k) * NPIX + i4];
        }
        for (int t = tx; t < 64 * 32 / 4; t += 256) {
            int o  = t >> 3;
            int k4 = (t & 7) << 2;
            float4 w = *(const float4*)&W[(size_t)(o0 + o) * CIN + k0 + k4];
            sWT[k4 + 0][o] = w.x; sWT[k4 + 1][o] = w.y;
            sWT[k4 + 2][o] = w.z; sWT[k4 + 3][o] = w.w;
        }
        __syncthreads();
#pragma unroll
        for (int k = 0; k < 32; k++) {
            float4 a = *(float4*)&sIn[k][ti * 4];
            float4 w = *(float4*)&sWT[k][to * 4];
            float av[4] = {a.x, a.y, a.z, a.w};
            float wv[4] = {w.x, w.y, w.z, w.w};
#pragma unroll
            for (int ii = 0; ii < 4; ii++)
#pragma unroll
                for (int oo = 0; oo < 4; oo++)
                    acc[ii][oo] = fmaf(av[ii], wv[oo], acc[ii][oo]);
        }
        __syncthreads();
    }

#pragma unroll
    for (int ii = 0; ii < 4; ii++)
#pragma unroll
        for (int oo = 0; oo < 4; oo++)
            sOut[ti * 4 + ii][to * 4 + oo] = acc[ii][oo];
    __syncthreads();

    for (int t = tx; t < 64 * 64 / 4; t += 256) {
        int i  = t >> 4;
        int o4 = (t & 15) << 2;
        float4 v = *(float4*)&sOut[i][o4];
        float4 bb = *(const float4*)&bias[o0 + o4];
        v.x = (v.x + bb.x) * scale;
        v.y = (v.y + bb.y) * scale;
        v.z = (v.z + bb.z) * scale;
        v.w = (v.w + bb.w) * scale;
        *(float4*)&out[((size_t)b * NPIX + i0 + i) * COUT + o0 + o4] = v;
    }
}

// ============================================================================
// Flash attention + fuse — BJ=32 for 2 CTAs/SM (93.4 KB smem each).
//   QK micro-tile 4x2 (i = ti+16*ii, j = tj+16*jj, jj 0..1).
//   PV warp-c specialization: warp w owns c in [32w,32w+32);
//     lane l: ig = l>>1, c0 = 32w + 16*(l&1). Conflict-free V loads.
// ============================================================================
#define BI 64
#define BJ 32
#define NT 256
#define SQ_STR 132   // 128 + 4 pad
#define SV_STR 256
#define SS_STR 36    // 32 + 4 pad

#define SMEM_FLOATS (BI*SQ_STR + BJ*SQ_STR + BJ*SV_STR + BI*SS_STR + 3*BI)
#define SMEM_BYTES  (SMEM_FLOATS * 4)

__global__ __launch_bounds__(NT, 2) void flash_kernel(
    const float* __restrict__ Q, const float* __restrict__ K,
    const float* __restrict__ V, const float* __restrict__ motion,
    float* __restrict__ out)
{
    extern __shared__ float smem[];
    float* sQ = smem;                      // [BI][SQ_STR]
    float* sK = sQ + BI * SQ_STR;          // [BJ][SQ_STR]
    float* sV = sK + BJ * SQ_STR;          // [BJ][SV_STR]
    float* sS = sV + BJ * SV_STR;          // [BI][SS_STR]
    float* sM = sS + BI * SS_STR;
    float* sL = sM + BI;
    float* sScale = sL + BI;

    const int b  = blockIdx.y;
    const int i0 = blockIdx.x * BI;
    const int tx = threadIdx.x;
    // QK-phase mapping
    const int ti = tx >> 4;    // 0..15
    const int tj = tx & 15;    // 0..15
    // PV-phase mapping (warp-c specialization)
    const int w  = tx >> 5;    // warp 0..7
    const int l  = tx & 31;
    const int ig = l >> 1;     // 0..15 : i = ig + 16*ii
    const int c0 = 32 * w + 16 * (l & 1);

    const float* Qb = Q + ((size_t)b * NPIX + i0) * CQK;
    const float* Kb = K + (size_t)b * NPIX * CQK;
    const float* Vb = V + (size_t)b * NPIX * CV;

    // load Q tile once
    for (int t = tx; t < BI * CQK / 4; t += NT) {
        int i  = t >> 5;
        int k4 = (t & 31) << 2;
        *(float4*)&sQ[i * SQ_STR + k4] = *(const float4*)&Qb[(size_t)i * CQK + k4];
    }
    if (tx < BI) { sM[tx] = -1e30f; sL[tx] = 0.0f; }

    // PV accumulators: i = ig + 16*ii ; c = c0 + 2*cc + {0,1}
    float2 acc[4][8];
#pragma unroll
    for (int ii = 0; ii < 4; ii++)
#pragma unroll
        for (int cc = 0; cc < 8; cc++) acc[ii][cc] = make_float2(0.0f, 0.0f);

    for (int j0 = 0; j0 < NPIX; j0 += BJ) {
        // ---- load K, V tiles ----
        for (int t = tx; t < BJ * CQK / 4; t += NT) {
            int j  = t >> 5;
            int k4 = (t & 31) << 2;
            *(float4*)&sK[j * SQ_STR + k4] = *(const float4*)&Kb[(size_t)(j0 + j) * CQK + k4];
        }
        for (int t = tx; t < BJ * CV / 4; t += NT) {
            int j  = t >> 6;
            int c4 = (t & 63) << 2;
            *(float4*)&sV[j * SV_STR + c4] = *(const float4*)&Vb[(size_t)(j0 + j) * CV + c4];
        }
        __syncthreads();

        // ---- S = Q Kt : 4x2 micro-tile, float2 accumulators along k ----
        {
            float2 sacc[4][2];
#pragma unroll
            for (int a = 0; a < 4; a++)
#pragma unroll
                for (int c = 0; c < 2; c++) sacc[a][c] = make_float2(0.0f, 0.0f);

#pragma unroll 8
            for (int k = 0; k < CQK; k += 4) {
                float4 qv[4], kv[2];
#pragma unroll
                for (int ii = 0; ii < 4; ii++)
                    qv[ii] = *(float4*)&sQ[(ti + 16 * ii) * SQ_STR + k];
#pragma unroll
                for (int jj = 0; jj < 2; jj++)
                    kv[jj] = *(float4*)&sK[(tj + 16 * jj) * SQ_STR + k];
#pragma unroll
                for (int ii = 0; ii < 4; ii++) {
                    float2 qlo = make_float2(qv[ii].x, qv[ii].y);
                    float2 qhi = make_float2(qv[ii].z, qv[ii].w);
#pragma unroll
                    for (int jj = 0; jj < 2; jj++) {
                        ffma2(sacc[ii][jj], qlo, make_float2(kv[jj].x, kv[jj].y));
                        ffma2(sacc[ii][jj], qhi, make_float2(kv[jj].z, kv[jj].w));
                    }
                }
            }
#pragma unroll
            for (int ii = 0; ii < 4; ii++)
#pragma unroll
                for (int jj = 0; jj < 2; jj++)
                    sS[(ti + 16 * ii) * SS_STR + (tj + 16 * jj)] =
                        sacc[ii][jj].x + sacc[ii][jj].y;
        }
        __syncthreads();

        // ---- online softmax (base-2): 4 threads per row, 8 cols each ----
        {
            const int r  = tx >> 2;
            const int qq = tx & 3;
            float* row = &sS[r * SS_STR + qq * 8];
            float4 v0 = *(float4*)&row[0];
            float4 v1 = *(float4*)&row[4];
            float mx = fmaxf(fmaxf(fmaxf(v0.x, v0.y), fmaxf(v0.z, v0.w)),
                             fmaxf(fmaxf(v1.x, v1.y), fmaxf(v1.z, v1.w)));
            mx = fmaxf(mx, __shfl_xor_sync(0xffffffffu, mx, 1));
            mx = fmaxf(mx, __shfl_xor_sync(0xffffffffu, mx, 2));
            float m_old = sM[r];
            float m_new = fmaxf(m_old, mx);
            v0.x = exp2_fast(v0.x - m_new);
            v0.y = exp2_fast(v0.y - m_new);
            v0.z = exp2_fast(v0.z - m_new);
            v0.w = exp2_fast(v0.w - m_new);
            v1.x = exp2_fast(v1.x - m_new);
            v1.y = exp2_fast(v1.y - m_new);
            v1.z = exp2_fast(v1.z - m_new);
            v1.w = exp2_fast(v1.w - m_new);
            float sum = ((v0.x + v0.y) + (v0.z + v0.w))
                      + ((v1.x + v1.y) + (v1.z + v1.w));
            *(float4*)&row[0] = v0;
            *(float4*)&row[4] = v1;
            sum += __shfl_xor_sync(0xffffffffu, sum, 1);
            sum += __shfl_xor_sync(0xffffffffu, sum, 2);
            if (qq == 0) {
                float scl = exp2_fast(m_old - m_new);
                sScale[r] = scl;
                sM[r] = m_new;
                sL[r] = sL[r] * scl + sum;
            }
        }
        __syncthreads();

        // ---- rescale accumulators, acc += P @ V (warp-c specialization) ----
        {
#pragma unroll
            for (int ii = 0; ii < 4; ii++) {
                float s = sScale[ig + 16 * ii];
                float2 s2 = make_float2(s, s);
#pragma unroll
                for (int cc = 0; cc < 8; cc++) fmul2(acc[ii][cc], s2);
            }

#pragma unroll
            for (int j = 0; j < BJ; j += 4) {
                float4 p4[4];
#pragma unroll
                for (int ii = 0; ii < 4; ii++)
                    p4[ii] = *(float4*)&sS[(ig + 16 * ii) * SS_STR + j];
#pragma unroll
                for (int e = 0; e < 4; e++) {
                    const float* vrow = &sV[(j + e) * SV_STR + c0];
                    float4 v0 = *(const float4*)&vrow[0];
                    float4 v1 = *(const float4*)&vrow[4];
                    float4 v2 = *(const float4*)&vrow[8];
                    float4 v3 = *(const float4*)&vrow[12];
                    float2 vv[8] = {
                        make_float2(v0.x, v0.y), make_float2(v0.z, v0.w),
                        make_float2(v1.x, v1.y), make_float2(v1.z, v1.w),
                        make_float2(v2.x, v2.y), make_float2(v2.z, v2.w),
                        make_float2(v3.x, v3.y), make_float2(v3.z, v3.w)};
#pragma unroll
                    for (int ii = 0; ii < 4; ii++) {
                        float pe = (e == 0) ? p4[ii].x : (e == 1) ? p4[ii].y
                                 : (e == 2) ? p4[ii].z : p4[ii].w;
                        float2 pp = make_float2(pe, pe);
#pragma unroll
                        for (int cc = 0; cc < 8; cc++)
                            ffma2(acc[ii][cc], pp, vv[cc]);
                    }
                }
            }
        }
        __syncthreads();
    }

    // ---- epilogue: normalize, transpose via smem, fused coalesced writes ----
    float rl[4];
#pragma unroll
    for (int ii = 0; ii < 4; ii++) rl[ii] = 1.0f / sL[ig + 16 * ii];

    // overlay at smem base: needs 256*68 = 17408 floats; sM/sL live at
    // offset 23168+ and are read into rl before any write below. The last
    // tile iteration ended with __syncthreads(), so sS reads are ordered.
    float* sT = smem;
#pragma unroll
    for (int ii = 0; ii < 4; ii++)
#pragma unroll
        for (int cc = 0; cc < 8; cc++) {
            int c = c0 + 2 * cc;
            sT[(c + 0) * (BI + 4) + (ig + 16 * ii)] = acc[ii][cc].x * rl[ii];
            sT[(c + 1) * (BI + 4) + (ig + 16 * ii)] = acc[ii][cc].y * rl[ii];
        }
    __syncthreads();

    float* attn_out = out + (size_t)BATCH * CV * NPIX;
    for (int t = tx; t < CV * BI / 4; t += NT) {
        int c  = t >> 4;
        int i4 = (t & 15) << 2;
        float4 v = *(float4*)&sT[c * (BI + 4) + i4];
        size_t g = ((size_t)b * CV + c) * NPIX + i0 + i4;
        float4 m = *(const float4*)&motion[g];
        float4 f;
        f.x = v.x * m.x; f.y = v.y * m.y; f.z = v.z * m.z; f.w = v.w * m.w;
        *(float4*)&out[g] = f;        // fuse_out
        *(float4*)&attn_out[g] = v;   // out
    }
}

// ============================================================================
extern "C" void kernel_launch(void* const* d_in, const int* in_sizes, int n_in,
                              void* d_out, int out_size)
{
    const float* a1  = (const float*)d_in[0];
    const float* a2  = (const float*)d_in[1];
    const float* mot = (const float*)d_in[2];
    const float* Wq  = (const float*)d_in[3];
    const float* bq  = (const float*)d_in[4];
    const float* Wk  = (const float*)d_in[5];
    const float* bk  = (const float*)d_in[6];
    const float* Wv  = (const float*)d_in[7];
    const float* bv  = (const float*)d_in[8];
    float* out = (float*)d_out;

    float *Qp, *Kp, *Vp;
    cudaGetSymbolAddress((void**)&Qp, g_Q);
    cudaGetSymbolAddress((void**)&Kp, g_K);
    cudaGetSymbolAddress((void**)&Vp, g_V);

    const float LOG2E = 1.4426950408889634f;

    proj_kernel<CQK, CQK><<<dim3(NPIX / 64, CQK / 64, BATCH), 256>>>(a2, Wq, bq, Qp, LOG2E);
    proj_kernel<CQK, CQK><<<dim3(NPIX / 64, CQK / 64, BATCH), 256>>>(a1, Wk, bk, Kp, 1.0f);
    proj_kernel<CV,  CV ><<<dim3(NPIX / 64, CV  / 64, BATCH), 256>>>(mot, Wv, bv, Vp, 1.0f);

    cudaFuncSetAttribute(flash_kernel, cudaFuncAttributeMaxDynamicSharedMemorySize, SMEM_BYTES);
    flash_kernel<<<dim3(NPIX / BI, BATCH), NT, SMEM_BYTES>>>(Qp, Kp, Vp, mot, out);
}

// round 14
// speedup vs baseline: 3.2612x; 2.2083x over previous
#include <cuda_runtime.h>
#include <cuda_bf16.h>
#include <cstdint>

#define BATCH 8
#define NPIX  4096
#define CQK   128
#define CV    256
#define BJ    64

__device__ __nv_bfloat16 g_Qhi[BATCH * NPIX * CQK];
__device__ __nv_bfloat16 g_Qlo[BATCH * NPIX * CQK];
__device__ __nv_bfloat16 g_Khi[BATCH * NPIX * CQK];
__device__ __nv_bfloat16 g_Klo[BATCH * NPIX * CQK];
__device__ __nv_bfloat16 g_Vthi[BATCH * CV * NPIX];  // [b][c][n] transposed
__device__ __nv_bfloat16 g_Vtlo[BATCH * CV * NPIX];

__device__ __forceinline__ uint32_t smem_u32(const void* p) {
    uint32_t a;
    asm("{ .reg .u64 t; cvta.to.shared.u64 t, %1; cvt.u32.u64 %0, t; }" : "=r"(a) : "l"(p));
    return a;
}
__device__ __forceinline__ void ldsm4(uint32_t r[4], uint32_t addr) {
    asm volatile("ldmatrix.sync.aligned.m8n8.x4.shared.b16 {%0,%1,%2,%3}, [%4];"
                 : "=r"(r[0]), "=r"(r[1]), "=r"(r[2]), "=r"(r[3]) : "r"(addr));
}
__device__ __forceinline__ void mma_bf16(float d[4], const uint32_t a[4],
                                         uint32_t b0, uint32_t b1) {
    asm("mma.sync.aligned.m16n8k16.row.col.f32.bf16.bf16.f32 "
        "{%0,%1,%2,%3}, {%4,%5,%6,%7}, {%8,%9}, {%0,%1,%2,%3};"
        : "+f"(d[0]), "+f"(d[1]), "+f"(d[2]), "+f"(d[3])
        : "r"(a[0]), "r"(a[1]), "r"(a[2]), "r"(a[3]), "r"(b0), "r"(b1));
}

__device__ __forceinline__ float exp2_fast(float x) {
    x = fmaxf(x, -126.0f);
    float fl = floorf(x), f = x - fl;
    float p = 1.87757667e-3f;
    p = fmaf(p, f, 8.98934058e-3f); p = fmaf(p, f, 5.58263180e-2f);
    p = fmaf(p, f, 2.40153617e-1f); p = fmaf(p, f, 6.93153073e-1f);
    p = fmaf(p, f, 9.99999994e-1f);
    return p * __int_as_float(((int)fl + 127) << 23);
}

// ============================================================================
// Projection -> bf16 hi/lo split. TR=false: [b][i][o]; TR=true: [b][o][i].
// ============================================================================
template<int CIN, int COUT, bool TR>
__global__ __launch_bounds__(256) void proj_split(
    const float* __restrict__ in, const float* __restrict__ W,
    const float* __restrict__ bias, __nv_bfloat16* __restrict__ ohi,
    __nv_bfloat16* __restrict__ olo, float scale)
{
    __shared__ float sIn[32][64], sWT[32][64], sOut[64][68];
    const int b = blockIdx.z, i0 = blockIdx.x * 64, o0 = blockIdx.y * 64;
    const int tx = threadIdx.x, ti = tx & 15, to = tx >> 4;
    const float* inb = in + (size_t)b * CIN * NPIX + i0;

    float acc[4][4];
#pragma unroll
    for (int a = 0; a < 4; a++)
#pragma unroll
        for (int c = 0; c < 4; c++) acc[a][c] = 0.0f;

    for (int k0 = 0; k0 < CIN; k0 += 32) {
        for (int t = tx; t < 512; t += 256) {
            int k = t >> 4, i4 = (t & 15) << 2;
            *(float4*)&sIn[k][i4] = *(const float4*)&inb[(size_t)(k0 + k) * NPIX + i4];
        }
        for (int t = tx; t < 512; t += 256) {
            int o = t >> 3, k4 = (t & 7) << 2;
            float4 w = *(const float4*)&W[(size_t)(o0 + o) * CIN + k0 + k4];
            sWT[k4][o] = w.x; sWT[k4 + 1][o] = w.y; sWT[k4 + 2][o] = w.z; sWT[k4 + 3][o] = w.w;
        }
        __syncthreads();
#pragma unroll
        for (int k = 0; k < 32; k++) {
            float4 a = *(float4*)&sIn[k][ti * 4];
            float4 w = *(float4*)&sWT[k][to * 4];
            float av[4] = {a.x, a.y, a.z, a.w}, wv[4] = {w.x, w.y, w.z, w.w};
#pragma unroll
            for (int ii = 0; ii < 4; ii++)
#pragma unroll
                for (int oo = 0; oo < 4; oo++)
                    acc[ii][oo] = fmaf(av[ii], wv[oo], acc[ii][oo]);
        }
        __syncthreads();
    }
#pragma unroll
    for (int ii = 0; ii < 4; ii++)
#pragma unroll
        for (int oo = 0; oo < 4; oo++)
            sOut[ti * 4 + ii][to * 4 + oo] = acc[ii][oo];
    __syncthreads();

    for (int t = tx; t < 1024; t += 256) {
        float x[4];
        size_t g;
        if (!TR) {
            int i = t >> 4, o4 = (t & 15) << 2;
            float4 v = *(float4*)&sOut[i][o4];
            float4 bb = *(const float4*)&bias[o0 + o4];
            x[0] = (v.x + bb.x) * scale; x[1] = (v.y + bb.y) * scale;
            x[2] = (v.z + bb.z) * scale; x[3] = (v.w + bb.w) * scale;
            g = ((size_t)b * NPIX + i0 + i) * COUT + o0 + o4;
        } else {
            int o = t >> 4, i4 = (t & 15) << 2;
            float bb = bias[o0 + o];
#pragma unroll
            for (int e = 0; e < 4; e++) x[e] = (sOut[i4 + e][o] + bb) * scale;
            g = ((size_t)b * COUT + o0 + o) * NPIX + i0 + i4;
        }
#pragma unroll
        for (int e = 0; e < 4; e++) {
            __nv_bfloat16 h = __float2bfloat16_rn(x[e]);
            ohi[g + e] = h;
            olo[g + e] = __float2bfloat16_rn(x[e] - __bfloat162float(h));
        }
    }
}

// ============================================================================
// HMMA flash attention + fuse. 256 threads / 8 warps, 128 i-rows per CTA.
// Q/K rows: 128 bf16 = 256B, padded stride 272B ((17r+k)%8 conflict-free).
// Vt rows: 64 bf16 = 128B, stride 144B ((9r+k)%8 conflict-free).
// ============================================================================
#define RQK 272
#define RV  144
#define SQH 0
#define SQL 34816
#define SKH 69632
#define SKL 87040
#define SVH 104448
#define SVL 141312
#define SMTOT 178176

__global__ __launch_bounds__(256, 1) void flash_hmma(
    const __nv_bfloat16* __restrict__ Qhi, const __nv_bfloat16* __restrict__ Qlo,
    const __nv_bfloat16* __restrict__ Khi, const __nv_bfloat16* __restrict__ Klo,
    const __nv_bfloat16* __restrict__ Vhi, const __nv_bfloat16* __restrict__ Vlo,
    const float* __restrict__ motion, float* __restrict__ out)
{
    extern __shared__ char smem[];
    const uint32_t sb = smem_u32(smem);
    const int tx = threadIdx.x, wid = tx >> 5, lane = tx & 31;
    const int b = blockIdx.y, i0 = blockIdx.x * 128;
    const int g = lane >> 2, t = lane & 3;
    const int mr = lane >> 3, rr = lane & 7;   // ldmatrix role: matrix idx, row

    // per-lane ldmatrix base addresses
    const uint32_t aQ = sb + SQH + (uint32_t)(wid * 16 + rr + (mr & 1) * 8) * RQK + (mr >> 1) * 16;
    const uint32_t aK = sb + SKH + (uint32_t)(rr + (mr >> 1) * 8) * RQK + (mr & 1) * 16;
    const uint32_t aV = sb + SVH + (uint32_t)(rr + (mr >> 1) * 8) * RV + (mr & 1) * 16;

    // fill Q (128 rows x 16 chunks of 16B), hi+lo
    {
        const size_t qb = ((size_t)b * NPIX + i0) * CQK;
        for (int it = tx; it < 2048; it += 256) {
            int row = it >> 4, ch = it & 15;
            uint32_t d = (uint32_t)row * RQK + ch * 16;
            size_t s = qb + (size_t)row * CQK + ch * 8;
            *(uint4*)(smem + SQH + d) = *(const uint4*)(Qhi + s);
            *(uint4*)(smem + SQL + d) = *(const uint4*)(Qlo + s);
        }
    }

    float D[32][4];
#pragma unroll
    for (int nb = 0; nb < 32; nb++)
#pragma unroll
        for (int e = 0; e < 4; e++) D[nb][e] = 0.0f;
    float L0 = 0.0f, L1 = 0.0f;

    for (int jt = 0; jt < NPIX / BJ; jt++) {
        __syncthreads();   // prev tile's V reads done before refill
        {
            const size_t kb = ((size_t)b * NPIX + jt * BJ) * CQK;
            for (int it = tx; it < 1024; it += 256) {
                int row = it >> 4, ch = it & 15;
                uint32_t d = (uint32_t)row * RQK + ch * 16;
                size_t s = kb + (size_t)row * CQK + ch * 8;
                *(uint4*)(smem + SKH + d) = *(const uint4*)(Khi + s);
                *(uint4*)(smem + SKL + d) = *(const uint4*)(Klo + s);
            }
            const size_t vb = (size_t)b * CV * NPIX + jt * BJ;
            for (int it = tx; it < 2048; it += 256) {
                int row = it >> 3, ch = it & 7;
                uint32_t d = (uint32_t)row * RV + ch * 16;
                size_t s = vb + (size_t)row * NPIX + ch * 8;
                *(uint4*)(smem + SVH + d) = *(const uint4*)(Vhi + s);
                *(uint4*)(smem + SVL + d) = *(const uint4*)(Vlo + s);
            }
        }
        __syncthreads();

        // ---- S = Q·K^T, 3-term bf16 split ----
        float S[8][4];
#pragma unroll
        for (int nb = 0; nb < 8; nb++)
#pragma unroll
            for (int e = 0; e < 4; e++) S[nb][e] = 0.0f;

#pragma unroll
        for (int s = 0; s < 8; s++) {
            uint32_t qh[4], ql[4];
            ldsm4(qh, aQ + s * 32);
            ldsm4(ql, aQ + (SQL - SQH) + s * 32);
#pragma unroll
            for (int jb2 = 0; jb2 < 4; jb2++) {
                uint32_t kh[4], kl[4];
                uint32_t ka = aK + (uint32_t)jb2 * (16 * RQK) + s * 32;
                ldsm4(kh, ka);
                ldsm4(kl, ka + (SKL - SKH));
                mma_bf16(S[2 * jb2],     qh, kh[0], kh[1]);
                mma_bf16(S[2 * jb2 + 1], qh, kh[2], kh[3]);
                mma_bf16(S[2 * jb2],     qh, kl[0], kl[1]);
                mma_bf16(S[2 * jb2 + 1], qh, kl[2], kl[3]);
                mma_bf16(S[2 * jb2],     ql, kh[0], kh[1]);
                mma_bf16(S[2 * jb2 + 1], ql, kh[2], kh[3]);
            }
        }

        // ---- softmax (no max-sub) + in-register P pack (hi trunc / lo resid) ----
        uint32_t Ph[4][4], Pl[4][4];
#pragma unroll
        for (int nb = 0; nb < 8; nb++) {
            float p0 = exp2_fast(S[nb][0]);
            float p1 = exp2_fast(S[nb][1]);
            float p2 = exp2_fast(S[nb][2]);
            float p3 = exp2_fast(S[nb][3]);
            L0 += p0 + p1; L1 += p2 + p3;
            uint32_t u0 = __float_as_uint(p0), u1 = __float_as_uint(p1);
            uint32_t u2 = __float_as_uint(p2), u3 = __float_as_uint(p3);
            float l0 = p0 - __uint_as_float(u0 & 0xFFFF0000u);
            float l1 = p1 - __uint_as_float(u1 & 0xFFFF0000u);
            float l2 = p2 - __uint_as_float(u2 & 0xFFFF0000u);
            float l3 = p3 - __uint_as_float(u3 & 0xFFFF0000u);
            int m = nb >> 1, sl = (nb & 1) * 2;
            Ph[m][sl]     = __byte_perm(u0, u1, 0x7632);
            Ph[m][sl + 1] = __byte_perm(u2, u3, 0x7632);
            uint32_t a, c;
            asm("cvt.rn.bf16x2.f32 %0, %1, %2;" : "=r"(a) : "f"(l1), "f"(l0));
            asm("cvt.rn.bf16x2.f32 %0, %1, %2;" : "=r"(c) : "f"(l3), "f"(l2));
            Pl[m][sl] = a; Pl[m][sl + 1] = c;
        }

        // ---- D += P·V^T, 3-term split ----
#pragma unroll
        for (int m = 0; m < 4; m++) {
#pragma unroll
            for (int cb2 = 0; cb2 < 16; cb2++) {
                uint32_t vh[4], vl[4];
                uint32_t va = aV + (uint32_t)cb2 * (16 * RV) + m * 32;
                ldsm4(vh, va);
                ldsm4(vl, va + (SVL - SVH));
                mma_bf16(D[2 * cb2],     Ph[m], vh[0], vh[1]);
                mma_bf16(D[2 * cb2 + 1], Ph[m], vh[2], vh[3]);
                mma_bf16(D[2 * cb2],     Ph[m], vl[0], vl[1]);
                mma_bf16(D[2 * cb2 + 1], Ph[m], vl[2], vl[3]);
                mma_bf16(D[2 * cb2],     Pl[m], vh[0], vh[1]);
                mma_bf16(D[2 * cb2 + 1], Pl[m], vh[2], vh[3]);
            }
        }
    }

    // ---- epilogue: reduce L over quad, normalize, fused writes ----
    L0 += __shfl_xor_sync(0xffffffffu, L0, 1);
    L0 += __shfl_xor_sync(0xffffffffu, L0, 2);
    L1 += __shfl_xor_sync(0xffffffffu, L1, 1);
    L1 += __shfl_xor_sync(0xffffffffu, L1, 2);
    const float inv0 = 1.0f / L0, inv1 = 1.0f / L1;
    const int ig0 = i0 + wid * 16 + g, ig8 = ig0 + 8;
    float* attn = out + (size_t)BATCH * CV * NPIX;
#pragma unroll
    for (int nb = 0; nb < 32; nb++) {
        int c = 8 * nb + 2 * t;
        size_t g0 = ((size_t)b * CV + c) * NPIX;
        float v00 = D[nb][0] * inv0, v01 = D[nb][1] * inv0;
        float v10 = D[nb][2] * inv1, v11 = D[nb][3] * inv1;
        out[g0 + ig0] = v00 * motion[g0 + ig0];               attn[g0 + ig0] = v00;
        out[g0 + NPIX + ig0] = v01 * motion[g0 + NPIX + ig0]; attn[g0 + NPIX + ig0] = v01;
        out[g0 + ig8] = v10 * motion[g0 + ig8];               attn[g0 + ig8] = v10;
        out[g0 + NPIX + ig8] = v11 * motion[g0 + NPIX + ig8]; attn[g0 + NPIX + ig8] = v11;
    }
}

// ============================================================================
extern "C" void kernel_launch(void* const* d_in, const int* in_sizes, int n_in,
                              void* d_out, int out_size)
{
    const float* a1  = (const float*)d_in[0];
    const float* a2  = (const float*)d_in[1];
    const float* mot = (const float*)d_in[2];
    const float* Wq  = (const float*)d_in[3];
    const float* bq  = (const float*)d_in[4];
    const float* Wk  = (const float*)d_in[5];
    const float* bk  = (const float*)d_in[6];
    const float* Wv  = (const float*)d_in[7];
    const float* bv  = (const float*)d_in[8];
    float* out = (float*)d_out;

    __nv_bfloat16 *Qh, *Ql, *Kh, *Kl, *Vh, *Vl;
    cudaGetSymbolAddress((void**)&Qh, g_Qhi);  cudaGetSymbolAddress((void**)&Ql, g_Qlo);
    cudaGetSymbolAddress((void**)&Kh, g_Khi);  cudaGetSymbolAddress((void**)&Kl, g_Klo);
    cudaGetSymbolAddress((void**)&Vh, g_Vthi); cudaGetSymbolAddress((void**)&Vl, g_Vtlo);

    const float LOG2E = 1.4426950408889634f;

    proj_split<CQK, CQK, false><<<dim3(NPIX / 64, 2, BATCH), 256>>>(a2, Wq, bq, Qh, Ql, LOG2E);
    proj_split<CQK, CQK, false><<<dim3(NPIX / 64, 2, BATCH), 256>>>(a1, Wk, bk, Kh, Kl, 1.0f);
    proj_split<CV,  CV,  true ><<<dim3(NPIX / 64, 4, BATCH), 256>>>(mot, Wv, bv, Vh, Vl, 1.0f);

    cudaFuncSetAttribute(flash_hmma, cudaFuncAttributeMaxDynamicSharedMemorySize, SMTOT);
    flash_hmma<<<dim3(NPIX / 128, BATCH), 256, SMTOT>>>(Qh, Ql, Kh, Kl, Vh, Vl, mot, out);
}